// round 6
// baseline (speedup 1.0000x reference)
#include <cuda_runtime.h>
#include <cstdint>

#define RNODES 256
#define LUTWORDS 8192        // 2^18 bits / 32
#define MSAMP 512
#define SSTEPS 512
#define NIN 32               // D*B
#define NOUT 10
#define SPC 4                // samples per CTA
#define NCTA (MSAMP / SPC)   // 128 -> single wave

// Persistent scratch (device globals — no runtime allocation allowed)
__device__ unsigned g_lutpk[RNODES * LUTWORDS];   // 8 MB bit-packed LUT
__device__ unsigned g_xbits[MSAMP * SSTEPS];      // 1 MB: 32 input bits per (m,t)
__device__ unsigned g_Wlo[64 * RNODES];           // chunk-major low bytes of primes*W
__device__ unsigned g_hib[24 * RNODES];           // [b(0..2)][w(0..7)][j] hi bitplanes
__device__ int g_is_u8;                           // bool serialization flag

// ---------------------------------------------------------------------------
// Detect whether bool tensors are serialized as 1-byte or 4-byte elements.
// ---------------------------------------------------------------------------
__global__ void k_detect(const void* xraw) {
    const unsigned char* p = (const unsigned char*)xraw;
    int t = threadIdx.x;
    int found = 0;
    for (int i = t; i < 4096; i += 256)
        if ((i & 3) && p[i]) found = 1;
    found = __syncthreads_or(found);
    if (t == 0) g_is_u8 = found ? 1 : 0;
}

// ---------------------------------------------------------------------------
// Pack the 256MB int32 0/1 LUT into 8MB of bits (fully coalesced, ballot).
// ---------------------------------------------------------------------------
__global__ void k_lutpack(const int* __restrict__ lut) {
    unsigned g = blockIdx.x * 256u + threadIdx.x;      // over 67,108,864
    unsigned v = (unsigned)lut[g] & 1u;
    unsigned m = __ballot_sync(0xffffffffu, v);
    if ((threadIdx.x & 31u) == 0u) g_lutpk[g >> 5] = m;
}

// ---------------------------------------------------------------------------
// Pack x[m, t, :] (32 bools) into one u32 per (m,t).
// ---------------------------------------------------------------------------
__global__ void k_xpack(const void* xraw) {
    unsigned g = blockIdx.x * 256u + threadIdx.x;      // over 8,388,608
    unsigned v;
    if (g_is_u8) v = ((const unsigned char*)xraw)[g] & 1u;
    else         v = (unsigned)((const int*)xraw)[g] & 1u;
    unsigned m = __ballot_sync(0xffffffffu, v);
    if ((threadIdx.x & 31u) == 0u) g_xbits[g >> 5] = m;
}

// ---------------------------------------------------------------------------
// Build weight structures. Wp[j,k] = W[j,k] ? primes[k] : 0, split as
//   lo = Wp & 255  -> chunk-major u32 (4 bytes of k per word) for dp4a
//   hi = Wp >> 8 (0..6) -> 3 bitplanes over k, 8 words of 32 bits each
// ---------------------------------------------------------------------------
__global__ void k_wprep(const void* wraw, const int* __restrict__ primes) {
    int t = blockIdx.x * 256 + threadIdx.x;            // 0..2047
    if (t >= RNODES * 8) return;
    int j = t >> 3, w = t & 7;
    unsigned lo[8] = {0, 0, 0, 0, 0, 0, 0, 0};
    unsigned hb0 = 0, hb1 = 0, hb2 = 0;
    int flag = g_is_u8;
    for (int kk = 0; kk < 32; kk++) {
        int k = w * 32 + kk;
        unsigned wv = flag ? (unsigned)(((const unsigned char*)wraw)[j * RNODES + k] & 1)
                           : ((unsigned)((const int*)wraw)[j * RNODES + k] & 1u);
        unsigned p = wv ? (unsigned)primes[k] : 0u;
        lo[kk >> 2] |= (p & 255u) << ((kk & 3) * 8);
        unsigned h = p >> 8;
        hb0 |= (h & 1u) << kk;
        hb1 |= ((h >> 1) & 1u) << kk;
        hb2 |= ((h >> 2) & 1u) << kk;
    }
    for (int cc = 0; cc < 8; cc++)
        g_Wlo[(w * 8 + cc) * RNODES + j] = lo[cc];
    g_hib[(0 * 8 + w) * RNODES + j] = hb0;
    g_hib[(1 * 8 + w) * RNODES + j] = hb1;
    g_hib[(2 * 8 + w) * RNODES + j] = hb2;
}

// ---------------------------------------------------------------------------
// Main reservoir kernel: 128 CTAs x 512 threads, 4 samples per CTA.
// Thread t = (node j = t&255, sample-pair p = t>>8). Each thread runs 2
// sample chains for its node -> 4 warps/SMSP of shorter streams for better
// latency hiding; weight registers (88) duplicated across the two halves.
// ---------------------------------------------------------------------------
__global__ void __launch_bounds__(512, 1)
k_main(const int* __restrict__ input_nodes,
       const void* __restrict__ initraw,
       const float* __restrict__ rW,
       const float* __restrict__ rb,
       float* __restrict__ out)
{
    __shared__ unsigned s_x[SPC][SSTEPS];                      // 8 KB
    __shared__ __align__(16) uint4 s_r4[2][SPC][16];           // [buf][samp] 256B r-bytes
    __shared__ __align__(16) unsigned s_rbits[2][SPC][8];      // [buf][samp] r-bits

    const int m0 = blockIdx.x * SPC;
    const int t = threadIdx.x;
    const int j = t & 255;              // node
    const int p = t >> 8;               // sample-pair 0/1 -> samples {2p, 2p+1}
    const int sA = p * 2, sB = sA + 1;
    const int lane = t & 31;
    const int wmod = (t >> 5) & 7;      // node-word index within sample group

    // stage all samples' packed inputs
#pragma unroll
    for (int s = 0; s < SPC; s++)
        for (int i = t; i < SSTEPS; i += 512)
            s_x[s][i] = g_xbits[(m0 + s) * SSTEPS + i];

    // weights into registers (static across all 512 steps)
    unsigned Wlo[64];
#pragma unroll
    for (int c = 0; c < 64; c++) Wlo[c] = g_Wlo[c * RNODES + j];
    unsigned HB0[8], HB1[8], HB2[8];
#pragma unroll
    for (int w = 0; w < 8; w++) {
        HB0[w] = g_hib[(0 * 8 + w) * RNODES + j];
        HB1[w] = g_hib[(1 * 8 + w) * RNODES + j];
        HB2[w] = g_hib[(2 * 8 + w) * RNODES + j];
    }

    // is this node an input node, and which bit does it take?
    int isin = 0, ipos = 0;
    for (int i = 0; i < NIN; i++) {
        int n = input_nodes[i];
        if (n == j) { isin = 1; ipos = i; }
    }

    const int flag = g_is_u8;
    unsigned rinit = flag ? (unsigned)(((const unsigned char*)initraw)[j] & 1)
                          : ((unsigned)((const int*)initraw)[j] & 1u);
    unsigned rA = rinit, rB = rinit;

    const unsigned* lutp = g_lutpk + ((unsigned)j << 13);

    __syncthreads();   // s_x visible before loop

    int buf = 0;
    for (int st = 0; st < SSTEPS; st++) {
        // (a) input overwrite for this thread's two samples
        unsigned xwA = s_x[sA][st], xwB = s_x[sB][st];
        if (isin) { rA = (xwA >> ipos) & 1u; rB = (xwB >> ipos) & 1u; }

        // publish r (bytes for dp4a, bits for popcount)
        unsigned bA = __ballot_sync(0xffffffffu, rA);
        unsigned bB = __ballot_sync(0xffffffffu, rB);
        ((unsigned char*)s_r4[buf][sA])[j] = (unsigned char)rA;
        ((unsigned char*)s_r4[buf][sB])[j] = (unsigned char)rB;
        if (lane == 0) { s_rbits[buf][sA][wmod] = bA; s_rbits[buf][sB][wmod] = bB; }
        __syncthreads();

        // (b) idx per own sample, LDG issued immediately after each idx
        unsigned idxA, idxB, wvA, wvB;
        {
            const uint4* q = s_r4[buf][sA];
            unsigned a0 = 0, a1 = 0, a2 = 0, a3 = 0;
#pragma unroll
            for (int c = 0; c < 16; c++) {
                uint4 v = q[c];
                a0 = __dp4a(v.x, Wlo[4 * c + 0], a0);
                a1 = __dp4a(v.y, Wlo[4 * c + 1], a1);
                a2 = __dp4a(v.z, Wlo[4 * c + 2], a2);
                a3 = __dp4a(v.w, Wlo[4 * c + 3], a3);
            }
            uint4 hA = *(const uint4*)&s_rbits[buf][sA][0];
            uint4 hB = *(const uint4*)&s_rbits[buf][sA][4];
            unsigned rw0 = hA.x, rw1 = hA.y, rw2 = hA.z, rw3 = hA.w;
            unsigned rw4 = hB.x, rw5 = hB.y, rw6 = hB.z, rw7 = hB.w;
            unsigned h0 = __popc(rw0 & HB0[0]) + __popc(rw1 & HB0[1]) +
                          __popc(rw2 & HB0[2]) + __popc(rw3 & HB0[3]) +
                          __popc(rw4 & HB0[4]) + __popc(rw5 & HB0[5]) +
                          __popc(rw6 & HB0[6]) + __popc(rw7 & HB0[7]);
            unsigned h1 = __popc(rw0 & HB1[0]) + __popc(rw1 & HB1[1]) +
                          __popc(rw2 & HB1[2]) + __popc(rw3 & HB1[3]) +
                          __popc(rw4 & HB1[4]) + __popc(rw5 & HB1[5]) +
                          __popc(rw6 & HB1[6]) + __popc(rw7 & HB1[7]);
            unsigned h2 = __popc(rw0 & HB2[0]) + __popc(rw1 & HB2[1]) +
                          __popc(rw2 & HB2[2]) + __popc(rw3 & HB2[3]) +
                          __popc(rw4 & HB2[4]) + __popc(rw5 & HB2[5]) +
                          __popc(rw6 & HB2[6]) + __popc(rw7 & HB2[7]);
            idxA = (a0 + a1) + (a2 + a3) + ((h0 + 2u * h1 + 4u * h2) << 8);
            wvA = __ldg(lutp + (idxA >> 5));
        }
        {
            const uint4* q = s_r4[buf][sB];
            unsigned a0 = 0, a1 = 0, a2 = 0, a3 = 0;
#pragma unroll
            for (int c = 0; c < 16; c++) {
                uint4 v = q[c];
                a0 = __dp4a(v.x, Wlo[4 * c + 0], a0);
                a1 = __dp4a(v.y, Wlo[4 * c + 1], a1);
                a2 = __dp4a(v.z, Wlo[4 * c + 2], a2);
                a3 = __dp4a(v.w, Wlo[4 * c + 3], a3);
            }
            uint4 hA = *(const uint4*)&s_rbits[buf][sB][0];
            uint4 hB = *(const uint4*)&s_rbits[buf][sB][4];
            unsigned rw0 = hA.x, rw1 = hA.y, rw2 = hA.z, rw3 = hA.w;
            unsigned rw4 = hB.x, rw5 = hB.y, rw6 = hB.z, rw7 = hB.w;
            unsigned h0 = __popc(rw0 & HB0[0]) + __popc(rw1 & HB0[1]) +
                          __popc(rw2 & HB0[2]) + __popc(rw3 & HB0[3]) +
                          __popc(rw4 & HB0[4]) + __popc(rw5 & HB0[5]) +
                          __popc(rw6 & HB0[6]) + __popc(rw7 & HB0[7]);
            unsigned h1 = __popc(rw0 & HB1[0]) + __popc(rw1 & HB1[1]) +
                          __popc(rw2 & HB1[2]) + __popc(rw3 & HB1[3]) +
                          __popc(rw4 & HB1[4]) + __popc(rw5 & HB1[5]) +
                          __popc(rw6 & HB1[6]) + __popc(rw7 & HB1[7]);
            unsigned h2 = __popc(rw0 & HB2[0]) + __popc(rw1 & HB2[1]) +
                          __popc(rw2 & HB2[2]) + __popc(rw3 & HB2[3]) +
                          __popc(rw4 & HB2[4]) + __popc(rw5 & HB2[5]) +
                          __popc(rw6 & HB2[6]) + __popc(rw7 & HB2[7]);
            idxB = (a0 + a1) + (a2 + a3) + ((h0 + 2u * h1 + 4u * h2) << 8);
            wvB = __ldg(lutp + (idxB >> 5));
        }

        rA = (wvA >> (idxA & 31u)) & 1u;
        rB = (wvB >> (idxB & 31u)) & 1u;
        buf ^= 1;
    }

    // publish final states
    ((unsigned char*)s_r4[buf][sA])[j] = (unsigned char)rA;
    ((unsigned char*)s_r4[buf][sB])[j] = (unsigned char)rB;
    __syncthreads();

    // readout: out[m, o] = sum_j rW[o, j] * rf[j] + rb[o]
    if (t < SPC * 16) {                        // 64 threads: sample = t/16, out = t%16
        int s = t >> 4, o = t & 15;
        if (o < NOUT) {
            const unsigned char* rf = (const unsigned char*)s_r4[buf][s];
            float acc = rb[o];
            const float* wr = rW + o * RNODES;
            for (int k = 0; k < RNODES; k++)
                acc += wr[k] * (float)rf[k];
            out[(m0 + s) * NOUT + o] = acc;
        }
    }
}

// ---------------------------------------------------------------------------
// d_in order: x, input_nodes, lut, W_res, primes, init_res, readout_W, readout_b
// ---------------------------------------------------------------------------
extern "C" void kernel_launch(void* const* d_in, const int* in_sizes, int n_in,
                              void* d_out, int out_size) {
    (void)in_sizes; (void)n_in; (void)out_size;
    const void*  x       = d_in[0];
    const int*   innodes = (const int*)d_in[1];
    const int*   lut     = (const int*)d_in[2];
    const void*  wres    = d_in[3];
    const int*   primes  = (const int*)d_in[4];
    const void*  initres = d_in[5];
    const float* rW      = (const float*)d_in[6];
    const float* rb      = (const float*)d_in[7];
    float* out = (float*)d_out;

    k_detect<<<1, 256>>>(x);
    k_lutpack<<<(RNODES * LUTWORDS * 32) / 256, 256>>>(lut);   // 262144 blocks
    k_xpack<<<(MSAMP * SSTEPS * 32) / 256, 256>>>(x);          // 32768 blocks
    k_wprep<<<8, 256>>>(wres, primes);
    k_main<<<NCTA, 512>>>(innodes, initres, rW, rb, out);
}

// round 9
// speedup vs baseline: 1.4913x; 1.4913x over previous
#include <cuda_runtime.h>
#include <cstdint>

#define RNODES 256
#define LUTWORDS 8192        // 2^18 bits / 32
#define MSAMP 512
#define SSTEPS 512
#define NIN 32               // D*B
#define NOUT 10
#define SPC 4                // samples per CTA
#define NCTA (MSAMP / SPC)   // 128 -> single wave, 1 CTA per SM

// Persistent scratch (device globals — no runtime allocation allowed)
__device__ unsigned g_lutpk[RNODES * LUTWORDS];   // 8 MB bit-packed LUT
__device__ unsigned g_xbits[MSAMP * SSTEPS];      // 1 MB: 32 input bits per (m,t)
__device__ unsigned g_Wlo[64 * RNODES];           // chunk-major low bytes of primes*W
__device__ unsigned g_hib[24 * RNODES];           // [b(0..2)][w(0..7)][j] hi bitplanes

// ---------------------------------------------------------------------------
// Per-warp bool-serialization detect: if x is int32-encoded, every byte at
// offset%4!=0 is zero. u8-encoded random bits false-negative prob ~2^-96.
// ---------------------------------------------------------------------------
__device__ __forceinline__ int detect_u8(const void* xraw) {
    const unsigned char* p = (const unsigned char*)xraw;
    unsigned lane = threadIdx.x & 31u;
    unsigned acc = 0;
    for (unsigned i = lane; i < 128; i += 32)
        if (i & 3) acc |= p[i];
    return __ballot_sync(0xffffffffu, acc != 0) != 0;
}

// ---------------------------------------------------------------------------
// Pack the 256MB int32 0/1 LUT into 8MB of bits (fully coalesced, ballot).
// ---------------------------------------------------------------------------
__global__ void k_lutpack(const int* __restrict__ lut) {
    unsigned g = blockIdx.x * 256u + threadIdx.x;      // over 67,108,864
    unsigned v = (unsigned)lut[g] & 1u;
    unsigned m = __ballot_sync(0xffffffffu, v);
    if ((threadIdx.x & 31u) == 0u) g_lutpk[g >> 5] = m;
}

// ---------------------------------------------------------------------------
// Fused prep: x bit-packing (grid-stride, 1024x256 threads, exactly 32 iters
// so ballots stay full-warp) + weight prep (first 2048 threads).
// ---------------------------------------------------------------------------
__global__ void k_prep(const void* __restrict__ xraw,
                       const void* __restrict__ wraw,
                       const int* __restrict__ primes) {
    const int flag = detect_u8(xraw);

    // ---- xpack: 8,388,608 bools -> 262,144 u32 words
    for (unsigned g = blockIdx.x * 256u + threadIdx.x;
         g < MSAMP * SSTEPS * 32u; g += 1024u * 256u) {
        unsigned v;
        if (flag) v = ((const unsigned char*)xraw)[g] & 1u;
        else      v = (unsigned)((const int*)xraw)[g] & 1u;
        unsigned m = __ballot_sync(0xffffffffu, v);
        if ((threadIdx.x & 31u) == 0u) g_xbits[g >> 5] = m;
    }

    // ---- wprep: Wp[j,k] = W[j,k] ? primes[k] : 0
    //   lo = Wp & 255  -> chunk-major u32 (4 bytes of k per word) for dp4a
    //   hi = Wp >> 8 (0..6) -> 3 bitplanes over k, 8 words of 32 bits each
    int t = blockIdx.x * 256 + threadIdx.x;
    if (t < RNODES * 8) {
        int j = t >> 3, w = t & 7;
        unsigned lo[8] = {0, 0, 0, 0, 0, 0, 0, 0};
        unsigned hb0 = 0, hb1 = 0, hb2 = 0;
        for (int kk = 0; kk < 32; kk++) {
            int k = w * 32 + kk;
            unsigned wv = flag ? (unsigned)(((const unsigned char*)wraw)[j * RNODES + k] & 1)
                               : ((unsigned)((const int*)wraw)[j * RNODES + k] & 1u);
            unsigned p = wv ? (unsigned)primes[k] : 0u;
            lo[kk >> 2] |= (p & 255u) << ((kk & 3) * 8);
            unsigned h = p >> 8;
            hb0 |= (h & 1u) << kk;
            hb1 |= ((h >> 1) & 1u) << kk;
            hb2 |= ((h >> 2) & 1u) << kk;
        }
        for (int cc = 0; cc < 8; cc++)
            g_Wlo[(w * 8 + cc) * RNODES + j] = lo[cc];
        g_hib[(0 * 8 + w) * RNODES + j] = hb0;
        g_hib[(1 * 8 + w) * RNODES + j] = hb1;
        g_hib[(2 * 8 + w) * RNODES + j] = hb2;
    }
}

// ---------------------------------------------------------------------------
// Main reservoir kernel: 4 samples per CTA, 128 CTAs, 256 threads (occ 1,
// full 255-reg budget, no spills). Software-pipelined over sample pairs:
// while pair B computes its index, pair A's LUT gathers drain, and vice
// versa. Two barriers per steady-state step.
// ---------------------------------------------------------------------------
__global__ void __launch_bounds__(256, 1)
k_main(const void* __restrict__ xraw,
       const int* __restrict__ input_nodes,
       const void* __restrict__ initraw,
       const float* __restrict__ rW,
       const float* __restrict__ rb,
       float* __restrict__ out)
{
    __shared__ unsigned s_x[SPC][SSTEPS];                      // 8 KB
    __shared__ __align__(16) uint4 s_r4[SPC][16];              // 256B r-bytes per sample
    __shared__ __align__(16) unsigned s_rbits[SPC][8];         // r-bits per sample

    const int m0 = blockIdx.x * SPC;
    const int j = threadIdx.x;
    const int lane = j & 31, warp = j >> 5;

    // stage all samples' packed inputs
#pragma unroll
    for (int s = 0; s < SPC; s++)
        for (int i = j; i < SSTEPS; i += 256)
            s_x[s][i] = g_xbits[(m0 + s) * SSTEPS + i];

    // weights into registers (static across all 512 steps)
    unsigned Wlo[64];
#pragma unroll
    for (int c = 0; c < 64; c++) Wlo[c] = g_Wlo[c * RNODES + j];
    unsigned HB0[8], HB1[8], HB2[8];
#pragma unroll
    for (int w = 0; w < 8; w++) {
        HB0[w] = g_hib[(0 * 8 + w) * RNODES + j];
        HB1[w] = g_hib[(1 * 8 + w) * RNODES + j];
        HB2[w] = g_hib[(2 * 8 + w) * RNODES + j];
    }

    int isin = 0, ipos = 0;
    for (int i = 0; i < NIN; i++) {
        int n = input_nodes[i];
        if (n == j) { isin = 1; ipos = i; }
    }

    const int flag = detect_u8(xraw);
    unsigned rinit = flag ? (unsigned)(((const unsigned char*)initraw)[j] & 1)
                          : ((unsigned)((const int*)initraw)[j] & 1u);
    unsigned r0 = rinit, r1 = rinit, r2 = rinit, r3 = rinit;

    const unsigned* lutp = g_lutpk + ((unsigned)j << 13);

    // dot for one sample from published shared state
    auto dot = [&](int s) -> unsigned {
        const uint4* q = s_r4[s];
        unsigned a0 = 0, a1 = 0, a2 = 0, a3 = 0;
#pragma unroll
        for (int c = 0; c < 16; c++) {
            uint4 v = q[c];
            a0 = __dp4a(v.x, Wlo[4 * c + 0], a0);
            a1 = __dp4a(v.y, Wlo[4 * c + 1], a1);
            a2 = __dp4a(v.z, Wlo[4 * c + 2], a2);
            a3 = __dp4a(v.w, Wlo[4 * c + 3], a3);
        }
        uint4 hA = *(const uint4*)&s_rbits[s][0];
        uint4 hB = *(const uint4*)&s_rbits[s][4];
        unsigned rw0 = hA.x, rw1 = hA.y, rw2 = hA.z, rw3 = hA.w;
        unsigned rw4 = hB.x, rw5 = hB.y, rw6 = hB.z, rw7 = hB.w;
        unsigned h0 = __popc(rw0 & HB0[0]) + __popc(rw1 & HB0[1]) +
                      __popc(rw2 & HB0[2]) + __popc(rw3 & HB0[3]) +
                      __popc(rw4 & HB0[4]) + __popc(rw5 & HB0[5]) +
                      __popc(rw6 & HB0[6]) + __popc(rw7 & HB0[7]);
        unsigned h1 = __popc(rw0 & HB1[0]) + __popc(rw1 & HB1[1]) +
                      __popc(rw2 & HB1[2]) + __popc(rw3 & HB1[3]) +
                      __popc(rw4 & HB1[4]) + __popc(rw5 & HB1[5]) +
                      __popc(rw6 & HB1[6]) + __popc(rw7 & HB1[7]);
        unsigned h2 = __popc(rw0 & HB2[0]) + __popc(rw1 & HB2[1]) +
                      __popc(rw2 & HB2[2]) + __popc(rw3 & HB2[3]) +
                      __popc(rw4 & HB2[4]) + __popc(rw5 & HB2[5]) +
                      __popc(rw6 & HB2[6]) + __popc(rw7 & HB2[7]);
        return (a0 + a1) + (a2 + a3) + ((h0 + 2u * h1 + 4u * h2) << 8);
    };
    auto publish = [&](int s, unsigned r) {
        unsigned b = __ballot_sync(0xffffffffu, r);
        ((unsigned char*)s_r4[s])[j] = (unsigned char)r;
        if (lane == 0) s_rbits[s][warp] = b;
    };

    __syncthreads();   // s_x visible

    // ---- prologue: apply input overwrite at t=0, publish all pairs
    {
        if (isin) {
            r0 = (s_x[0][0] >> ipos) & 1u;
            r1 = (s_x[1][0] >> ipos) & 1u;
            r2 = (s_x[2][0] >> ipos) & 1u;
            r3 = (s_x[3][0] >> ipos) & 1u;
        }
        publish(0, r0); publish(1, r1); publish(2, r2); publish(3, r3);
    }
    __syncthreads();

    // prime pair A (samples 0,1): idx + gather for step 0
    unsigned idx0 = dot(0), idx1 = dot(1);
    unsigned wv0 = __ldg(lutp + (idx0 >> 5));
    unsigned wv1 = __ldg(lutp + (idx1 >> 5));
    __syncthreads();   // all pre-loop reads of s_r4[0/1] done before loop rewrites them

    for (int t = 0; t < SSTEPS; t++) {
        // ---- phase 1: pair B compute+gather for step t (A loads drain under it)
        unsigned idx2 = dot(2), idx3 = dot(3);
        unsigned wv2 = __ldg(lutp + (idx2 >> 5));
        unsigned wv3 = __ldg(lutp + (idx3 >> 5));

        // consume A(step t) -> state t+1, overwrite, publish
        r0 = (wv0 >> (idx0 & 31u)) & 1u;
        r1 = (wv1 >> (idx1 & 31u)) & 1u;
        if (isin && t + 1 < SSTEPS) {
            r0 = (s_x[0][t + 1] >> ipos) & 1u;
            r1 = (s_x[1][t + 1] >> ipos) & 1u;
        }
        publish(0, r0); publish(1, r1);
        __syncthreads();

        // ---- phase 2: pair A compute+gather for step t+1 (B loads drain under it)
        idx0 = dot(0); idx1 = dot(1);
        wv0 = __ldg(lutp + (idx0 >> 5));
        wv1 = __ldg(lutp + (idx1 >> 5));

        // consume B(step t) -> state t+1, overwrite, publish
        r2 = (wv2 >> (idx2 & 31u)) & 1u;
        r3 = (wv3 >> (idx3 & 31u)) & 1u;
        if (isin && t + 1 < SSTEPS) {
            r2 = (s_x[2][t + 1] >> ipos) & 1u;
            r3 = (s_x[3][t + 1] >> ipos) & 1u;
        }
        publish(2, r2); publish(3, r3);
        __syncthreads();
    }

    // final states of all 4 samples are published in s_r4
    // readout: out[m, o] = sum_j rW[o, j] * rf[j] + rb[o]
    if (j < SPC * 16) {                        // 64 threads: sample = j/16, out = j%16
        int s = j >> 4, o = j & 15;
        if (o < NOUT) {
            const unsigned char* rf = (const unsigned char*)s_r4[s];
            float acc = rb[o];
            const float* wr = rW + o * RNODES;
            for (int k = 0; k < RNODES; k++)
                acc += wr[k] * (float)rf[k];
            out[(m0 + s) * NOUT + o] = acc;
        }
    }
}

// ---------------------------------------------------------------------------
// d_in order: x, input_nodes, lut, W_res, primes, init_res, readout_W, readout_b
// 3 launches per call: lutpack, prep, main (so ncu -s 5 -c 1 lands on k_main).
// ---------------------------------------------------------------------------
extern "C" void kernel_launch(void* const* d_in, const int* in_sizes, int n_in,
                              void* d_out, int out_size) {
    (void)in_sizes; (void)n_in; (void)out_size;
    const void*  x       = d_in[0];
    const int*   innodes = (const int*)d_in[1];
    const int*   lut     = (const int*)d_in[2];
    const void*  wres    = d_in[3];
    const int*   primes  = (const int*)d_in[4];
    const void*  initres = d_in[5];
    const float* rW      = (const float*)d_in[6];
    const float* rb      = (const float*)d_in[7];
    float* out = (float*)d_out;

    k_lutpack<<<(RNODES * LUTWORDS * 32) / 256, 256>>>(lut);   // 262144 blocks
    k_prep<<<1024, 256>>>(x, wres, primes);
    k_main<<<NCTA, 256>>>(x, innodes, initres, rW, rb, out);
}

// round 10
// speedup vs baseline: 1.6900x; 1.1333x over previous
#include <cuda_runtime.h>
#include <cstdint>

#define RNODES 256
#define LUTWORDS 8192        // 2^18 bits / 32
#define MSAMP 512
#define SSTEPS 512
#define NIN 32               // D*B
#define NOUT 10
#define SPC 4                // samples per CTA
#define NCTA (MSAMP / SPC)   // 128 -> single wave, 1 CTA per SM

// Persistent scratch (device globals — no runtime allocation allowed)
__device__ unsigned g_lutpk[RNODES * LUTWORDS];   // 8 MB bit-packed LUT
__device__ unsigned g_xbits[MSAMP * SSTEPS];      // 1 MB: 32 input bits per (m,t)
__device__ unsigned g_Wlo[64 * RNODES];           // chunk-major low bytes of primes*W
__device__ unsigned g_hib[24 * RNODES];           // [b(0..2)][w(0..7)][j] hi bitplanes

// ---------------------------------------------------------------------------
// Per-warp bool-serialization detect: if x is int32-encoded, every byte at
// offset%4!=0 is zero. u8-encoded random bits false-negative prob ~2^-96.
// ---------------------------------------------------------------------------
__device__ __forceinline__ int detect_u8(const void* xraw) {
    const unsigned char* p = (const unsigned char*)xraw;
    unsigned lane = threadIdx.x & 31u;
    unsigned acc = 0;
    for (unsigned i = lane; i < 128; i += 32)
        if (i & 3) acc |= p[i];
    return __ballot_sync(0xffffffffu, acc != 0) != 0;
}

// ---------------------------------------------------------------------------
// Pack the 256MB int32 0/1 LUT into 8MB of bits. 8 elements per thread,
// 32768 CTAs (the old 262144-CTA version was CTA-launch-throughput bound at
// ~1 CTA/cyc = 155us). 8 independent LDGs per thread for MLP; ballot packing.
// Word mapping: element g = T + i*8388608 -> word (T>>5) + i*262144.
// ---------------------------------------------------------------------------
__global__ void k_lutpack(const int* __restrict__ lut) {
    unsigned T = blockIdx.x * 256u + threadIdx.x;          // 8,388,608 threads
    unsigned v[8];
#pragma unroll
    for (int i = 0; i < 8; i++)
        v[i] = (unsigned)lut[T + (unsigned)i * 8388608u];
    unsigned wbase = T >> 5;
#pragma unroll
    for (int i = 0; i < 8; i++) {
        unsigned m = __ballot_sync(0xffffffffu, v[i] & 1u);
        if ((threadIdx.x & 31u) == 0u)
            g_lutpk[wbase + (unsigned)i * 262144u] = m;
    }
}

// ---------------------------------------------------------------------------
// Fused prep: x bit-packing (grid-stride, 1024x256 threads, exactly 32 iters
// so ballots stay full-warp) + weight prep (first 2048 threads).
// ---------------------------------------------------------------------------
__global__ void k_prep(const void* __restrict__ xraw,
                       const void* __restrict__ wraw,
                       const int* __restrict__ primes) {
    const int flag = detect_u8(xraw);

    // ---- xpack: 8,388,608 bools -> 262,144 u32 words
    for (unsigned g = blockIdx.x * 256u + threadIdx.x;
         g < MSAMP * SSTEPS * 32u; g += 1024u * 256u) {
        unsigned v;
        if (flag) v = ((const unsigned char*)xraw)[g] & 1u;
        else      v = (unsigned)((const int*)xraw)[g] & 1u;
        unsigned m = __ballot_sync(0xffffffffu, v);
        if ((threadIdx.x & 31u) == 0u) g_xbits[g >> 5] = m;
    }

    // ---- wprep: Wp[j,k] = W[j,k] ? primes[k] : 0
    //   lo = Wp & 255  -> chunk-major u32 (4 bytes of k per word) for dp4a
    //   hi = Wp >> 8 (0..6) -> 3 bitplanes over k, 8 words of 32 bits each
    int t = blockIdx.x * 256 + threadIdx.x;
    if (t < RNODES * 8) {
        int j = t >> 3, w = t & 7;
        unsigned lo[8] = {0, 0, 0, 0, 0, 0, 0, 0};
        unsigned hb0 = 0, hb1 = 0, hb2 = 0;
        for (int kk = 0; kk < 32; kk++) {
            int k = w * 32 + kk;
            unsigned wv = flag ? (unsigned)(((const unsigned char*)wraw)[j * RNODES + k] & 1)
                               : ((unsigned)((const int*)wraw)[j * RNODES + k] & 1u);
            unsigned p = wv ? (unsigned)primes[k] : 0u;
            lo[kk >> 2] |= (p & 255u) << ((kk & 3) * 8);
            unsigned h = p >> 8;
            hb0 |= (h & 1u) << kk;
            hb1 |= ((h >> 1) & 1u) << kk;
            hb2 |= ((h >> 2) & 1u) << kk;
        }
        for (int cc = 0; cc < 8; cc++)
            g_Wlo[(w * 8 + cc) * RNODES + j] = lo[cc];
        g_hib[(0 * 8 + w) * RNODES + j] = hb0;
        g_hib[(1 * 8 + w) * RNODES + j] = hb1;
        g_hib[(2 * 8 + w) * RNODES + j] = hb2;
    }
}

// ---------------------------------------------------------------------------
// Main reservoir kernel: 4 samples per CTA, 128 CTAs, 256 threads (occ 1,
// full 255-reg budget, no spills). Software-pipelined over sample pairs:
// while pair B computes its index, pair A's LUT gathers drain, and vice
// versa. Two barriers per steady-state step.
// ---------------------------------------------------------------------------
__global__ void __launch_bounds__(256, 1)
k_main(const void* __restrict__ xraw,
       const int* __restrict__ input_nodes,
       const void* __restrict__ initraw,
       const float* __restrict__ rW,
       const float* __restrict__ rb,
       float* __restrict__ out)
{
    __shared__ unsigned s_x[SPC][SSTEPS];                      // 8 KB
    __shared__ __align__(16) uint4 s_r4[SPC][16];              // 256B r-bytes per sample
    __shared__ __align__(16) unsigned s_rbits[SPC][8];         // r-bits per sample

    const int m0 = blockIdx.x * SPC;
    const int j = threadIdx.x;
    const int lane = j & 31, warp = j >> 5;

    // stage all samples' packed inputs
#pragma unroll
    for (int s = 0; s < SPC; s++)
        for (int i = j; i < SSTEPS; i += 256)
            s_x[s][i] = g_xbits[(m0 + s) * SSTEPS + i];

    // weights into registers (static across all 512 steps)
    unsigned Wlo[64];
#pragma unroll
    for (int c = 0; c < 64; c++) Wlo[c] = g_Wlo[c * RNODES + j];
    unsigned HB0[8], HB1[8], HB2[8];
#pragma unroll
    for (int w = 0; w < 8; w++) {
        HB0[w] = g_hib[(0 * 8 + w) * RNODES + j];
        HB1[w] = g_hib[(1 * 8 + w) * RNODES + j];
        HB2[w] = g_hib[(2 * 8 + w) * RNODES + j];
    }

    int isin = 0, ipos = 0;
    for (int i = 0; i < NIN; i++) {
        int n = input_nodes[i];
        if (n == j) { isin = 1; ipos = i; }
    }

    const int flag = detect_u8(xraw);
    unsigned rinit = flag ? (unsigned)(((const unsigned char*)initraw)[j] & 1)
                          : ((unsigned)((const int*)initraw)[j] & 1u);
    unsigned r0 = rinit, r1 = rinit, r2 = rinit, r3 = rinit;

    const unsigned* lutp = g_lutpk + ((unsigned)j << 13);

    // dot for one sample from published shared state
    auto dot = [&](int s) -> unsigned {
        const uint4* q = s_r4[s];
        unsigned a0 = 0, a1 = 0, a2 = 0, a3 = 0;
#pragma unroll
        for (int c = 0; c < 16; c++) {
            uint4 v = q[c];
            a0 = __dp4a(v.x, Wlo[4 * c + 0], a0);
            a1 = __dp4a(v.y, Wlo[4 * c + 1], a1);
            a2 = __dp4a(v.z, Wlo[4 * c + 2], a2);
            a3 = __dp4a(v.w, Wlo[4 * c + 3], a3);
        }
        uint4 hA = *(const uint4*)&s_rbits[s][0];
        uint4 hB = *(const uint4*)&s_rbits[s][4];
        unsigned rw0 = hA.x, rw1 = hA.y, rw2 = hA.z, rw3 = hA.w;
        unsigned rw4 = hB.x, rw5 = hB.y, rw6 = hB.z, rw7 = hB.w;
        unsigned h0 = __popc(rw0 & HB0[0]) + __popc(rw1 & HB0[1]) +
                      __popc(rw2 & HB0[2]) + __popc(rw3 & HB0[3]) +
                      __popc(rw4 & HB0[4]) + __popc(rw5 & HB0[5]) +
                      __popc(rw6 & HB0[6]) + __popc(rw7 & HB0[7]);
        unsigned h1 = __popc(rw0 & HB1[0]) + __popc(rw1 & HB1[1]) +
                      __popc(rw2 & HB1[2]) + __popc(rw3 & HB1[3]) +
                      __popc(rw4 & HB1[4]) + __popc(rw5 & HB1[5]) +
                      __popc(rw6 & HB1[6]) + __popc(rw7 & HB1[7]);
        unsigned h2 = __popc(rw0 & HB2[0]) + __popc(rw1 & HB2[1]) +
                      __popc(rw2 & HB2[2]) + __popc(rw3 & HB2[3]) +
                      __popc(rw4 & HB2[4]) + __popc(rw5 & HB2[5]) +
                      __popc(rw6 & HB2[6]) + __popc(rw7 & HB2[7]);
        return (a0 + a1) + (a2 + a3) + ((h0 + 2u * h1 + 4u * h2) << 8);
    };
    auto publish = [&](int s, unsigned r) {
        unsigned b = __ballot_sync(0xffffffffu, r);
        ((unsigned char*)s_r4[s])[j] = (unsigned char)r;
        if (lane == 0) s_rbits[s][warp] = b;
    };

    __syncthreads();   // s_x visible

    // ---- prologue: apply input overwrite at t=0, publish all pairs
    {
        if (isin) {
            r0 = (s_x[0][0] >> ipos) & 1u;
            r1 = (s_x[1][0] >> ipos) & 1u;
            r2 = (s_x[2][0] >> ipos) & 1u;
            r3 = (s_x[3][0] >> ipos) & 1u;
        }
        publish(0, r0); publish(1, r1); publish(2, r2); publish(3, r3);
    }
    __syncthreads();

    // prime pair A (samples 0,1): idx + gather for step 0
    unsigned idx0 = dot(0), idx1 = dot(1);
    unsigned wv0 = __ldg(lutp + (idx0 >> 5));
    unsigned wv1 = __ldg(lutp + (idx1 >> 5));
    __syncthreads();   // all pre-loop reads of s_r4[0/1] done before loop rewrites them

    for (int t = 0; t < SSTEPS; t++) {
        // ---- phase 1: pair B compute+gather for step t (A loads drain under it)
        unsigned idx2 = dot(2), idx3 = dot(3);
        unsigned wv2 = __ldg(lutp + (idx2 >> 5));
        unsigned wv3 = __ldg(lutp + (idx3 >> 5));

        // consume A(step t) -> state t+1, overwrite, publish
        r0 = (wv0 >> (idx0 & 31u)) & 1u;
        r1 = (wv1 >> (idx1 & 31u)) & 1u;
        if (isin && t + 1 < SSTEPS) {
            r0 = (s_x[0][t + 1] >> ipos) & 1u;
            r1 = (s_x[1][t + 1] >> ipos) & 1u;
        }
        publish(0, r0); publish(1, r1);
        __syncthreads();

        // ---- phase 2: pair A compute+gather for step t+1 (B loads drain under it)
        idx0 = dot(0); idx1 = dot(1);
        wv0 = __ldg(lutp + (idx0 >> 5));
        wv1 = __ldg(lutp + (idx1 >> 5));

        // consume B(step t) -> state t+1, overwrite, publish
        r2 = (wv2 >> (idx2 & 31u)) & 1u;
        r3 = (wv3 >> (idx3 & 31u)) & 1u;
        if (isin && t + 1 < SSTEPS) {
            r2 = (s_x[2][t + 1] >> ipos) & 1u;
            r3 = (s_x[3][t + 1] >> ipos) & 1u;
        }
        publish(2, r2); publish(3, r3);
        __syncthreads();
    }

    // final states of all 4 samples are published in s_r4
    // readout: out[m, o] = sum_j rW[o, j] * rf[j] + rb[o]
    if (j < SPC * 16) {                        // 64 threads: sample = j/16, out = j%16
        int s = j >> 4, o = j & 15;
        if (o < NOUT) {
            const unsigned char* rf = (const unsigned char*)s_r4[s];
            float acc = rb[o];
            const float* wr = rW + o * RNODES;
            for (int k = 0; k < RNODES; k++)
                acc += wr[k] * (float)rf[k];
            out[(m0 + s) * NOUT + o] = acc;
        }
    }
}

// ---------------------------------------------------------------------------
// d_in order: x, input_nodes, lut, W_res, primes, init_res, readout_W, readout_b
// 3 launches per call: lutpack, prep, main.
// ---------------------------------------------------------------------------
extern "C" void kernel_launch(void* const* d_in, const int* in_sizes, int n_in,
                              void* d_out, int out_size) {
    (void)in_sizes; (void)n_in; (void)out_size;
    const void*  x       = d_in[0];
    const int*   innodes = (const int*)d_in[1];
    const int*   lut     = (const int*)d_in[2];
    const void*  wres    = d_in[3];
    const int*   primes  = (const int*)d_in[4];
    const void*  initres = d_in[5];
    const float* rW      = (const float*)d_in[6];
    const float* rb      = (const float*)d_in[7];
    float* out = (float*)d_out;

    k_lutpack<<<32768, 256>>>(lut);            // 8 elems/thread, launch-rate safe
    k_prep<<<1024, 256>>>(x, wres, primes);
    k_main<<<NCTA, 256>>>(x, innodes, initres, rW, rb, out);
}